// round 1
// baseline (speedup 1.0000x reference)
#include <cuda_runtime.h>

// InvConditionalLinear forward: per-pixel 32x32 solve W z = x + sum log|det W|.
// B=16, C=32, H=W=48. Output: z [B,C,H,W] (1179648 floats) then logdet-wl [B] (16 floats).
//
// One warp per pixel matrix, lane i owns row i in registers (fully unrolled
// Gauss-Jordan, all register indices static). Unpivoted: W = I + 0.1*N(0,1)
// is well conditioned. log|det| = sum log|pivot|.

#define FULL_MASK 0xffffffffu

static constexpr int B = 16, C = 32, HW = 48 * 48;   // HW = 2304
static constexpr int PIX_PER_BLK = 8;                // 2304 % 8 == 0 -> never straddles batch
static constexpr int MAT_STRIDE = 1057;              // 33*32 + 1: conflict-free both access patterns
static constexpr int ROW_STRIDE = 33;

static __device__ float g_pixlogdet[B * HW];         // per-pixel log|det| scratch

__global__ __launch_bounds__(256) void gj_solve_kernel(
    const float* __restrict__ input,   // [B, C, H, W]
    const float* __restrict__ weight,  // [B, C*C, H, W]
    float* __restrict__ out)           // [B, C, H, W] region of d_out
{
    __shared__ float s_w[PIX_PER_BLK * MAT_STRIDE];
    __shared__ float s_x[PIX_PER_BLK * ROW_STRIDE];
    __shared__ float s_z[PIX_PER_BLK * ROW_STRIDE];

    const int t    = threadIdx.x;
    const int lane = t & 31;
    const int p    = t >> 5;                 // warp id = pixel within block
    const int q0   = blockIdx.x * PIX_PER_BLK;
    const int b    = q0 / HW;
    const int qm0  = q0 - b * HW;            // h*48 + w of first pixel

    // ---- Phase 1: coalesced load of 8 matrices (8192 floats) + 8 rhs vectors ----
    // weight[b, c, h, w] at (b*1024 + c)*2304 + (h*48+w). Vectorize over the
    // pixel axis (contiguous): float4 covers pixels pp..pp+3 of channel c.
    const float* wbase = weight + (size_t)b * (size_t)(C * C) * HW + qm0;
    #pragma unroll
    for (int it = 0; it < 8; ++it) {
        int idx = it * 256 + t;              // 0..2047 float4 loads
        int c   = idx >> 1;                  // channel 0..1023
        int pp  = (idx & 1) << 2;            // pixel 0 or 4
        float4 v = *reinterpret_cast<const float4*>(wbase + (size_t)c * HW + pp);
        int sb = (c >> 5) * ROW_STRIDE + (c & 31);   // row i = c>>5, col j = c&31
        s_w[(pp + 0) * MAT_STRIDE + sb] = v.x;
        s_w[(pp + 1) * MAT_STRIDE + sb] = v.y;
        s_w[(pp + 2) * MAT_STRIDE + sb] = v.z;
        s_w[(pp + 3) * MAT_STRIDE + sb] = v.w;
    }
    {
        int c = t >> 3, pp = t & 7;
        s_x[pp * ROW_STRIDE + c] =
            input[(size_t)b * C * HW + (size_t)c * HW + qm0 + pp];
    }
    __syncthreads();

    // ---- Phase 2: register-resident Gauss-Jordan, lane = row ----
    float a[32];
    const float* mr = s_w + p * MAT_STRIDE + lane * ROW_STRIDE;
    #pragma unroll
    for (int j = 0; j < 32; ++j) a[j] = mr[j];   // stride-33: conflict-free
    float rhs = s_x[p * ROW_STRIDE + lane];

    float mypinv = 0.0f;
    float mylog  = 0.0f;
    #pragma unroll
    for (int k = 0; k < 32; ++k) {
        float piv  = __shfl_sync(FULL_MASK, a[k], k);
        float pinv = __fdividef(1.0f, piv);
        if (lane == k) { mypinv = pinv; mylog = logf(fabsf(piv)); }
        float m = (lane == k) ? 0.0f : a[k] * pinv;
        #pragma unroll
        for (int j = k + 1; j < 32; ++j)
            a[j] = fmaf(-m, __shfl_sync(FULL_MASK, a[j], k), a[j]);
        rhs = fmaf(-m, __shfl_sync(FULL_MASK, rhs, k), rhs);
    }
    // System reduced to diag(piv_i) z_i = rhs_i
    float z = rhs * mypinv;

    // per-matrix log|det| = sum over lanes of mylog (each lane logged its own pivot)
    float s = mylog;
    #pragma unroll
    for (int off = 16; off; off >>= 1) s += __shfl_xor_sync(FULL_MASK, s, off);
    if (lane == 0) g_pixlogdet[q0 + p] = s;

    s_z[p * ROW_STRIDE + lane] = z;
    __syncthreads();

    // ---- Phase 3: coalesced store of z ----
    {
        int c = t >> 3, pp = t & 7;
        out[(size_t)b * C * HW + (size_t)c * HW + qm0 + pp] = s_z[pp * ROW_STRIDE + c];
    }
}

// Deterministic fixed-order per-batch reduction of 2304 pixel logdets.
__global__ __launch_bounds__(256) void logdet_reduce_kernel(
    const float* __restrict__ logdet_in, float* __restrict__ out)
{
    __shared__ float sm[256];
    const int b = blockIdx.x, t = threadIdx.x;
    float s = 0.0f;
    #pragma unroll
    for (int r = 0; r < 9; ++r)                 // 2304 = 9 * 256
        s += g_pixlogdet[b * HW + r * 256 + t];
    sm[t] = s;
    __syncthreads();
    #pragma unroll
    for (int off = 128; off; off >>= 1) {
        if (t < off) sm[t] += sm[t + off];
        __syncthreads();
    }
    if (t == 0) out[(size_t)B * C * HW + b] = logdet_in[b] - sm[0];
}

extern "C" void kernel_launch(void* const* d_in, const int* in_sizes, int n_in,
                              void* d_out, int out_size)
{
    const float* input  = (const float*)d_in[0];
    const float* weight = (const float*)d_in[1];
    const float* logdet = (const float*)d_in[2];
    float* out = (float*)d_out;

    gj_solve_kernel<<<(B * HW) / PIX_PER_BLK, 256>>>(input, weight, out);
    logdet_reduce_kernel<<<B, 256>>>(logdet, out);
}